// round 8
// baseline (speedup 1.0000x reference)
#include <cuda_runtime.h>
#include <cuda_bf16.h>
#include <math.h>

#define MAXN 100000
#define MAXE 1600000
#define MAXG 512
#define D 128
#define CH 2048   // nodes per CSR-build block

// ---------------- device scratch (no runtime allocation allowed) ----------------
__device__ __align__(128) float g_h[MAXN * D];     // current activation
__device__ __align__(128) float g_t[MAXN * D];     // gemm output h = in @ W
__device__ __align__(16)  int   g_deg[MAXN];       // in-degree (edges only)
__device__ __align__(16)  int   g_rowstart[MAXN + 1];
__device__ __align__(16)  float g_dis[MAXN];       // (deg+1)^-1/2
__device__ __align__(16)  int2  g_csr[MAXE];       // {src, __float_as_int(coef)}
__device__ __align__(16)  float g_dot[MAXN];       // per-node pooled dot

// ---------------- degree: block owns node range, shared-mem histogram ----------
__global__ __launch_bounds__(1024) void deg_shared_kernel(
    const int* __restrict__ dst, int n_edges, int n_nodes)
{
    __shared__ int hist[CH];
    int base = blockIdx.x * CH;
    for (int i = threadIdx.x; i < CH; i += blockDim.x) hist[i] = 0;
    __syncthreads();

    for (int e = threadIdx.x; e < n_edges; e += blockDim.x) {
        int d = dst[e] - base;
        if ((unsigned)d < (unsigned)CH) atomicAdd(&hist[d], 1);
    }
    __syncthreads();

    for (int i = threadIdx.x; i < CH; i += blockDim.x) {
        int node = base + i;
        if (node < n_nodes) g_deg[node] = hist[i];
    }
}

// ---------------- single-block exclusive scan -> rowstart ----------------
__global__ __launch_bounds__(1024) void scan_kernel(int n) {
    __shared__ int sh[1024];
    int t = threadIdx.x;
    int chunk = (n + 1023) / 1024;
    int lo = t * chunk;
    int hi = lo + chunk; if (hi > n) hi = n;
    int sum = 0;
    for (int i = lo; i < hi; i++) sum += g_deg[i];
    sh[t] = sum;
    __syncthreads();
    for (int off = 1; off < 1024; off <<= 1) {
        int v = (t >= off) ? sh[t - off] : 0;
        __syncthreads();
        if (t >= off) sh[t] += v;
        __syncthreads();
    }
    int run = (t == 0) ? 0 : sh[t - 1];
    for (int i = lo; i < hi; i++) { g_rowstart[i] = run; run += g_deg[i]; }
    if (lo < n && hi == n) g_rowstart[n] = run;
}

// ---------------- dis = rsqrt(deg + 1 self loop) ----------------
__global__ void dis_kernel(int n_nodes) {
    int i = blockIdx.x * blockDim.x + threadIdx.x;
    if (i < n_nodes) g_dis[i] = rsqrtf((float)(g_deg[i] + 1));
}

// ---------------- fill CSR: block owns node range, shared-mem cursors ----------
__global__ __launch_bounds__(1024) void fill_shared_kernel(
    const int* __restrict__ src, const int* __restrict__ dst,
    int n_edges, int n_nodes)
{
    __shared__ int cur[CH];
    int base = blockIdx.x * CH;
    for (int i = threadIdx.x; i < CH; i += blockDim.x) cur[i] = 0;
    __syncthreads();

    for (int e = threadIdx.x; e < n_edges; e += blockDim.x) {
        int dg = dst[e];
        int d = dg - base;
        if ((unsigned)d < (unsigned)CH) {
            int s = src[e];
            int pos = atomicAdd(&cur[d], 1);
            s = (unsigned)s < (unsigned)MAXN ? s : 0;    // defensive clamp
            float coef = g_dis[s] * g_dis[dg];
            int idx = g_rowstart[dg] + pos;
            idx = idx < (MAXE - 1) ? idx : (MAXE - 1);   // defensive clamp
            g_csr[idx] = make_int2(s, __float_as_int(coef));
        }
    }
}

// ---------------- GEMM: t = X @ W (X==nullptr -> g_h) ----------------
#define BM 64
#define BK 8
__global__ __launch_bounds__(256) void gemm_kernel(
    const float* __restrict__ Xin, const float* __restrict__ W, int nrows)
{
    const float* X = (Xin != nullptr) ? Xin : (const float*)g_h;

    __shared__ float Xs[BM][BK + 1];
    __shared__ float Ws[BK][D];

    int tid = threadIdx.x;
    int row0 = blockIdx.x * BM;
    int ty = tid >> 4;
    int tx = tid & 15;

    float acc[4][8];
    #pragma unroll
    for (int i = 0; i < 4; i++)
        #pragma unroll
        for (int j = 0; j < 8; j++) acc[i][j] = 0.0f;

    for (int kk = 0; kk < D; kk += BK) {
        {
            int idx = tid * 2;
            int m = idx >> 3, k = idx & 7;
            int r = row0 + m;
            float2 v = make_float2(0.0f, 0.0f);
            if (r < nrows) v = *(const float2*)&X[r * D + kk + k];
            Xs[m][k] = v.x; Xs[m][k + 1] = v.y;
        }
        {
            int idx = tid * 4;
            int k = idx >> 7, nn = idx & 127;
            *(float4*)&Ws[k][nn] = *(const float4*)&W[(kk + k) * D + nn];
        }
        __syncthreads();
        #pragma unroll
        for (int k = 0; k < BK; k++) {
            float a[4];
            #pragma unroll
            for (int i = 0; i < 4; i++) a[i] = Xs[ty * 4 + i][k];
            float4 b0 = *(float4*)&Ws[k][tx * 8];
            float4 b1 = *(float4*)&Ws[k][tx * 8 + 4];
            float bv[8] = {b0.x, b0.y, b0.z, b0.w, b1.x, b1.y, b1.z, b1.w};
            #pragma unroll
            for (int i = 0; i < 4; i++)
                #pragma unroll
                for (int j = 0; j < 8; j++) acc[i][j] = fmaf(a[i], bv[j], acc[i][j]);
        }
        __syncthreads();
    }

    #pragma unroll
    for (int i = 0; i < 4; i++) {
        int r = row0 + ty * 4 + i;
        if (r < nrows) {
            #pragma unroll
            for (int j = 0; j < 8; j += 4) {
                int c = tx * 8 + j;
                float4 t;
                t.x = acc[i][j]; t.y = acc[i][j+1]; t.z = acc[i][j+2]; t.w = acc[i][j+3];
                *(float4*)&g_t[r * D + c] = t;
            }
        }
    }
}

// ------- fused gather + self-loop + bias + layernorm (+res)(+relu)(+pool) -------
// one warp per node; lane handles feature lane*4..lane*4+3
template <bool RES, bool RELU, bool POOL>
__global__ __launch_bounds__(256) void gather_post_kernel(
    const float* __restrict__ bias,
    const float* __restrict__ gamma, const float* __restrict__ beta,
    const float* __restrict__ lin_w, int n_nodes)
{
    int lane = threadIdx.x & 31;
    int row = (blockIdx.x * blockDim.x + threadIdx.x) >> 5;
    if (row >= n_nodes) return;

    float di = g_dis[row];
    float d2 = di * di;
    float4 t4 = *(const float4*)&g_t[row * D + lane * 4];
    float4 b4 = *(const float4*)&bias[lane * 4];
    float ax = t4.x * d2 + b4.x;
    float ay = t4.y * d2 + b4.y;
    float az = t4.z * d2 + b4.z;
    float aw = t4.w * d2 + b4.w;

    int s0 = g_rowstart[row];
    int s1 = g_rowstart[row + 1];
    for (int i = s0; i < s1; i += 32) {
        int rem = s1 - i;
        int2 ent = make_int2(0, 0);
        if (lane < rem) ent = g_csr[i + lane];
        int cnt = rem < 32 ? rem : 32;
        for (int j = 0; j < cnt; j++) {
            int   s = __shfl_sync(0xffffffffu, ent.x, j);
            float c = __int_as_float(__shfl_sync(0xffffffffu, ent.y, j));
            s = (unsigned)s < (unsigned)MAXN ? s : 0;   // defensive clamp
            float4 v = *(const float4*)&g_t[s * D + lane * 4];
            ax = fmaf(v.x, c, ax);
            ay = fmaf(v.y, c, ay);
            az = fmaf(v.z, c, az);
            aw = fmaf(v.w, c, aw);
        }
    }

    float s = ax + ay + az + aw;
    #pragma unroll
    for (int o = 16; o; o >>= 1) s += __shfl_xor_sync(0xffffffffu, s, o);
    float mu = s * (1.0f / 128.0f);

    float dx = ax - mu, dy = ay - mu, dz = az - mu, dw = aw - mu;
    float q = dx * dx + dy * dy + dz * dz + dw * dw;
    #pragma unroll
    for (int o = 16; o; o >>= 1) q += __shfl_xor_sync(0xffffffffu, q, o);
    float rinv = rsqrtf(q * (1.0f / 128.0f) + 1e-5f);

    float4 g4 = *(const float4*)&gamma[lane * 4];
    float4 e4 = *(const float4*)&beta[lane * 4];
    float yx = dx * rinv * g4.x + e4.x;
    float yy = dy * rinv * g4.y + e4.y;
    float yz = dz * rinv * g4.z + e4.z;
    float yw = dw * rinv * g4.w + e4.w;

    if (RES) {
        float4 h4 = *(const float4*)&g_h[row * D + lane * 4];
        yx += h4.x; yy += h4.y; yz += h4.z; yw += h4.w;
    }
    if (RELU) {
        yx = fmaxf(yx, 0.0f); yy = fmaxf(yy, 0.0f);
        yz = fmaxf(yz, 0.0f); yw = fmaxf(yw, 0.0f);
    }
    *(float4*)&g_h[row * D + lane * 4] = make_float4(yx, yy, yz, yw);

    if (POOL) {
        float4 w4 = *(const float4*)&lin_w[lane * 4];
        float dot = yx * w4.x + yy * w4.y + yz * w4.z + yw * w4.w;
        #pragma unroll
        for (int o = 16; o; o >>= 1) dot += __shfl_xor_sync(0xffffffffu, dot, o);
        if (lane == 0) g_dot[row] = dot;
    }
}

// ---------------- per-graph mean pool via binary search on sorted batch ---------
__global__ __launch_bounds__(256) void pool_kernel(
    const int* __restrict__ batch, const float* __restrict__ lin_b,
    float* __restrict__ out, int n_nodes, int n_graphs)
{
    int lane = threadIdx.x & 31;
    int g = (blockIdx.x * blockDim.x + threadIdx.x) >> 5;
    if (g >= n_graphs) return;

    int lo = 0, hi = n_nodes;
    while (lo < hi) { int m = (lo + hi) >> 1; if (batch[m] < g) lo = m + 1; else hi = m; }
    int beg = lo;
    lo = beg; hi = n_nodes;
    while (lo < hi) { int m = (lo + hi) >> 1; if (batch[m] < g + 1) lo = m + 1; else hi = m; }
    int end = lo;

    float sum = 0.0f;
    for (int i = beg + lane; i < end; i += 32) sum += g_dot[i];
    #pragma unroll
    for (int o = 16; o; o >>= 1) sum += __shfl_xor_sync(0xffffffffu, sum, o);

    if (lane == 0) {
        float cnt = (float)(end - beg);
        out[g] = sum / fmaxf(cnt, 1.0f) + lin_b[0];
    }
}

// ---------------- launch ----------------
extern "C" void kernel_launch(void* const* d_in, const int* in_sizes, int n_in,
                              void* d_out, int out_size)
{
    const float* x      = (const float*)d_in[0];
    const int*   ei     = (const int*)d_in[1];     // int32! (harness converts int64)
    const int*   batch  = (const int*)d_in[2];     // int32!
    const float* Ws     = (const float*)d_in[3];
    const float* bs     = (const float*)d_in[4];
    const float* gammas = (const float*)d_in[5];
    const float* betas  = (const float*)d_in[6];
    const float* lin_w  = (const float*)d_in[7];
    const float* lin_b  = (const float*)d_in[8];
    float* out = (float*)d_out;

    int n_nodes  = in_sizes[0] / D;
    int n_edges  = in_sizes[1] / 2;
    int n_graphs = out_size;

    const int* src = ei;
    const int* dst = ei + n_edges;

    int csr_blocks = (n_nodes + CH - 1) / CH;
    deg_shared_kernel<<<csr_blocks, 1024>>>(dst, n_edges, n_nodes);
    scan_kernel<<<1, 1024>>>(n_nodes);
    dis_kernel<<<(n_nodes + 255) / 256, 256>>>(n_nodes);
    fill_shared_kernel<<<csr_blocks, 1024>>>(src, dst, n_edges, n_nodes);

    int gemm_blocks = (n_nodes + BM - 1) / BM;
    int warp_blocks = (n_nodes * 32 + 255) / 256;

    for (int L = 0; L < 4; L++) {
        const float* in = (L == 0) ? x : nullptr;  // nullptr -> g_h inside kernel
        gemm_kernel<<<gemm_blocks, 256>>>(in, Ws + L * D * D, n_nodes);
        if (L == 0)
            gather_post_kernel<false, true, false><<<warp_blocks, 256>>>(
                bs + L * D, gammas + L * D, betas + L * D, lin_w, n_nodes);
        else if (L < 3)
            gather_post_kernel<true, true, false><<<warp_blocks, 256>>>(
                bs + L * D, gammas + L * D, betas + L * D, lin_w, n_nodes);
        else
            gather_post_kernel<true, false, true><<<warp_blocks, 256>>>(
                bs + L * D, gammas + L * D, betas + L * D, lin_w, n_nodes);
    }

    pool_kernel<<<(n_graphs * 32 + 255) / 256, 256>>>(batch, lin_b, out, n_nodes, n_graphs);
}

// round 10
// speedup vs baseline: 1.4137x; 1.4137x over previous
#include <cuda_runtime.h>
#include <cuda_bf16.h>
#include <math.h>

#define MAXN 100000
#define MAXE 1600000
#define MAXG 512
#define D 128

// ---------------- device scratch (no runtime allocation allowed) ----------------
__device__ __align__(128) float g_h[MAXN * D];     // current activation
__device__ __align__(128) float g_t[MAXN * D];     // gemm output h = in @ W
__device__ __align__(16)  int   g_deg[MAXN];       // in-degree (edges only)
__device__ __align__(16)  int   g_rowstart[MAXN + 1];
__device__ __align__(16)  int   g_cursor[MAXN];
__device__ __align__(16)  float g_dis[MAXN];       // (deg+1)^-1/2
__device__ __align__(16)  int2  g_csr[MAXE];       // {src, __float_as_int(coef)}
__device__ __align__(16)  float g_dot[MAXN];       // per-node pooled dot

// ---------------- init: zero degree + cursors ----------------
__global__ void init_kernel(int n_nodes) {
    int i = blockIdx.x * blockDim.x + threadIdx.x;
    if (i < n_nodes) { g_deg[i] = 0; g_cursor[i] = 0; }
}

// ---------------- degree: one pass, global int atomics ----------------
__global__ void degree_kernel(const int* __restrict__ dst, int n_edges) {
    int e = blockIdx.x * blockDim.x + threadIdx.x;
    if (e >= n_edges) return;
    int d = dst[e];
    if ((unsigned)d < (unsigned)MAXN) atomicAdd(&g_deg[d], 1);
}

// ---------------- single-block exclusive scan -> rowstart ----------------
__global__ __launch_bounds__(1024) void scan_kernel(int n) {
    __shared__ int sh[1024];
    int t = threadIdx.x;
    int chunk = (n + 1023) / 1024;
    int lo = t * chunk;
    int hi = lo + chunk; if (hi > n) hi = n;
    int sum = 0;
    for (int i = lo; i < hi; i++) sum += g_deg[i];
    sh[t] = sum;
    __syncthreads();
    for (int off = 1; off < 1024; off <<= 1) {
        int v = (t >= off) ? sh[t - off] : 0;
        __syncthreads();
        if (t >= off) sh[t] += v;
        __syncthreads();
    }
    int run = (t == 0) ? 0 : sh[t - 1];
    for (int i = lo; i < hi; i++) { g_rowstart[i] = run; run += g_deg[i]; }
    if (lo < n && hi == n) g_rowstart[n] = run;
}

// ---------------- dis = rsqrt(deg + 1 self loop) ----------------
__global__ void dis_kernel(int n_nodes) {
    int i = blockIdx.x * blockDim.x + threadIdx.x;
    if (i < n_nodes) g_dis[i] = rsqrtf((float)(g_deg[i] + 1));
}

// ---------------- fill CSR: one pass, global int atomic cursors ----------------
__global__ void fill_kernel(const int* __restrict__ src,
                            const int* __restrict__ dst, int n_edges) {
    int e = blockIdx.x * blockDim.x + threadIdx.x;
    if (e >= n_edges) return;
    int s = src[e];
    int dg = dst[e];
    if ((unsigned)dg >= (unsigned)MAXN) return;
    s = (unsigned)s < (unsigned)MAXN ? s : 0;        // defensive clamp
    int pos = atomicAdd(&g_cursor[dg], 1);
    float coef = g_dis[s] * g_dis[dg];
    int idx = g_rowstart[dg] + pos;
    idx = idx < (MAXE - 1) ? idx : (MAXE - 1);       // defensive clamp
    g_csr[idx] = make_int2(s, __float_as_int(coef));
}

// ---------------- GEMM: t = X @ W (X==nullptr -> g_h) ----------------
#define BM 64
#define BK 8
__global__ __launch_bounds__(256) void gemm_kernel(
    const float* __restrict__ Xin, const float* __restrict__ W, int nrows)
{
    const float* X = (Xin != nullptr) ? Xin : (const float*)g_h;

    __shared__ float Xs[BM][BK + 1];
    __shared__ float Ws[BK][D];

    int tid = threadIdx.x;
    int row0 = blockIdx.x * BM;
    int ty = tid >> 4;
    int tx = tid & 15;

    float acc[4][8];
    #pragma unroll
    for (int i = 0; i < 4; i++)
        #pragma unroll
        for (int j = 0; j < 8; j++) acc[i][j] = 0.0f;

    for (int kk = 0; kk < D; kk += BK) {
        {
            int idx = tid * 2;
            int m = idx >> 3, k = idx & 7;
            int r = row0 + m;
            float2 v = make_float2(0.0f, 0.0f);
            if (r < nrows) v = *(const float2*)&X[r * D + kk + k];
            Xs[m][k] = v.x; Xs[m][k + 1] = v.y;
        }
        {
            int idx = tid * 4;
            int k = idx >> 7, nn = idx & 127;
            *(float4*)&Ws[k][nn] = *(const float4*)&W[(kk + k) * D + nn];
        }
        __syncthreads();
        #pragma unroll
        for (int k = 0; k < BK; k++) {
            float a[4];
            #pragma unroll
            for (int i = 0; i < 4; i++) a[i] = Xs[ty * 4 + i][k];
            float4 b0 = *(float4*)&Ws[k][tx * 8];
            float4 b1 = *(float4*)&Ws[k][tx * 8 + 4];
            float bv[8] = {b0.x, b0.y, b0.z, b0.w, b1.x, b1.y, b1.z, b1.w};
            #pragma unroll
            for (int i = 0; i < 4; i++)
                #pragma unroll
                for (int j = 0; j < 8; j++) acc[i][j] = fmaf(a[i], bv[j], acc[i][j]);
        }
        __syncthreads();
    }

    #pragma unroll
    for (int i = 0; i < 4; i++) {
        int r = row0 + ty * 4 + i;
        if (r < nrows) {
            #pragma unroll
            for (int j = 0; j < 8; j += 4) {
                int c = tx * 8 + j;
                float4 t;
                t.x = acc[i][j]; t.y = acc[i][j+1]; t.z = acc[i][j+2]; t.w = acc[i][j+3];
                *(float4*)&g_t[r * D + c] = t;
            }
        }
    }
}

// ------- fused gather + self-loop + bias + layernorm (+res)(+relu)(+pool) -------
// one warp per node; lane handles feature lane*4..lane*4+3
template <bool RES, bool RELU, bool POOL>
__global__ __launch_bounds__(256) void gather_post_kernel(
    const float* __restrict__ bias,
    const float* __restrict__ gamma, const float* __restrict__ beta,
    const float* __restrict__ lin_w, int n_nodes)
{
    int lane = threadIdx.x & 31;
    int row = (blockIdx.x * blockDim.x + threadIdx.x) >> 5;
    if (row >= n_nodes) return;

    float di = g_dis[row];
    float d2 = di * di;
    float4 t4 = *(const float4*)&g_t[row * D + lane * 4];
    float4 b4 = *(const float4*)&bias[lane * 4];
    float ax = t4.x * d2 + b4.x;
    float ay = t4.y * d2 + b4.y;
    float az = t4.z * d2 + b4.z;
    float aw = t4.w * d2 + b4.w;

    int s0 = g_rowstart[row];
    int s1 = g_rowstart[row + 1];
    for (int i = s0; i < s1; i += 32) {
        int rem = s1 - i;
        int2 ent = make_int2(0, 0);
        if (lane < rem) ent = g_csr[i + lane];
        int cnt = rem < 32 ? rem : 32;
        for (int j = 0; j < cnt; j++) {
            int   s = __shfl_sync(0xffffffffu, ent.x, j);
            float c = __int_as_float(__shfl_sync(0xffffffffu, ent.y, j));
            s = (unsigned)s < (unsigned)MAXN ? s : 0;   // defensive clamp
            float4 v = *(const float4*)&g_t[s * D + lane * 4];
            ax = fmaf(v.x, c, ax);
            ay = fmaf(v.y, c, ay);
            az = fmaf(v.z, c, az);
            aw = fmaf(v.w, c, aw);
        }
    }

    float s = ax + ay + az + aw;
    #pragma unroll
    for (int o = 16; o; o >>= 1) s += __shfl_xor_sync(0xffffffffu, s, o);
    float mu = s * (1.0f / 128.0f);

    float dx = ax - mu, dy = ay - mu, dz = az - mu, dw = aw - mu;
    float q = dx * dx + dy * dy + dz * dz + dw * dw;
    #pragma unroll
    for (int o = 16; o; o >>= 1) q += __shfl_xor_sync(0xffffffffu, q, o);
    float rinv = rsqrtf(q * (1.0f / 128.0f) + 1e-5f);

    float4 g4 = *(const float4*)&gamma[lane * 4];
    float4 e4 = *(const float4*)&beta[lane * 4];
    float yx = dx * rinv * g4.x + e4.x;
    float yy = dy * rinv * g4.y + e4.y;
    float yz = dz * rinv * g4.z + e4.z;
    float yw = dw * rinv * g4.w + e4.w;

    if (RES) {
        float4 h4 = *(const float4*)&g_h[row * D + lane * 4];
        yx += h4.x; yy += h4.y; yz += h4.z; yw += h4.w;
    }
    if (RELU) {
        yx = fmaxf(yx, 0.0f); yy = fmaxf(yy, 0.0f);
        yz = fmaxf(yz, 0.0f); yw = fmaxf(yw, 0.0f);
    }
    *(float4*)&g_h[row * D + lane * 4] = make_float4(yx, yy, yz, yw);

    if (POOL) {
        float4 w4 = *(const float4*)&lin_w[lane * 4];
        float dot = yx * w4.x + yy * w4.y + yz * w4.z + yw * w4.w;
        #pragma unroll
        for (int o = 16; o; o >>= 1) dot += __shfl_xor_sync(0xffffffffu, dot, o);
        if (lane == 0) g_dot[row] = dot;
    }
}

// ---------------- per-graph mean pool via binary search on sorted batch ---------
__global__ __launch_bounds__(256) void pool_kernel(
    const int* __restrict__ batch, const float* __restrict__ lin_b,
    float* __restrict__ out, int n_nodes, int n_graphs)
{
    int lane = threadIdx.x & 31;
    int g = (blockIdx.x * blockDim.x + threadIdx.x) >> 5;
    if (g >= n_graphs) return;

    int lo = 0, hi = n_nodes;
    while (lo < hi) { int m = (lo + hi) >> 1; if (batch[m] < g) lo = m + 1; else hi = m; }
    int beg = lo;
    lo = beg; hi = n_nodes;
    while (lo < hi) { int m = (lo + hi) >> 1; if (batch[m] < g + 1) lo = m + 1; else hi = m; }
    int end = lo;

    float sum = 0.0f;
    for (int i = beg + lane; i < end; i += 32) sum += g_dot[i];
    #pragma unroll
    for (int o = 16; o; o >>= 1) sum += __shfl_xor_sync(0xffffffffu, sum, o);

    if (lane == 0) {
        float cnt = (float)(end - beg);
        out[g] = sum / fmaxf(cnt, 1.0f) + lin_b[0];
    }
}

// ---------------- launch ----------------
extern "C" void kernel_launch(void* const* d_in, const int* in_sizes, int n_in,
                              void* d_out, int out_size)
{
    const float* x      = (const float*)d_in[0];
    const int*   ei     = (const int*)d_in[1];     // int32 (harness converts int64)
    const int*   batch  = (const int*)d_in[2];     // int32
    const float* Ws     = (const float*)d_in[3];
    const float* bs     = (const float*)d_in[4];
    const float* gammas = (const float*)d_in[5];
    const float* betas  = (const float*)d_in[6];
    const float* lin_w  = (const float*)d_in[7];
    const float* lin_b  = (const float*)d_in[8];
    float* out = (float*)d_out;

    int n_nodes  = in_sizes[0] / D;
    int n_edges  = in_sizes[1] / 2;
    int n_graphs = out_size;

    const int* src = ei;
    const int* dst = ei + n_edges;

    // ---- CSR build: single-pass global-atomic version ----
    init_kernel<<<(n_nodes + 255) / 256, 256>>>(n_nodes);
    degree_kernel<<<(n_edges + 255) / 256, 256>>>(dst, n_edges);
    scan_kernel<<<1, 1024>>>(n_nodes);
    dis_kernel<<<(n_nodes + 255) / 256, 256>>>(n_nodes);
    fill_kernel<<<(n_edges + 255) / 256, 256>>>(src, dst, n_edges);

    int gemm_blocks = (n_nodes + BM - 1) / BM;
    int warp_blocks = (n_nodes * 32 + 255) / 256;

    for (int L = 0; L < 4; L++) {
        const float* in = (L == 0) ? x : nullptr;  // nullptr -> g_h inside kernel
        gemm_kernel<<<gemm_blocks, 256>>>(in, Ws + L * D * D, n_nodes);
        if (L == 0)
            gather_post_kernel<false, true, false><<<warp_blocks, 256>>>(
                bs + L * D, gammas + L * D, betas + L * D, lin_w, n_nodes);
        else if (L < 3)
            gather_post_kernel<true, true, false><<<warp_blocks, 256>>>(
                bs + L * D, gammas + L * D, betas + L * D, lin_w, n_nodes);
        else
            gather_post_kernel<true, false, true><<<warp_blocks, 256>>>(
                bs + L * D, gammas + L * D, betas + L * D, lin_w, n_nodes);
    }

    pool_kernel<<<(n_graphs * 32 + 255) / 256, 256>>>(batch, lin_b, out, n_nodes, n_graphs);
}